// round 1
// baseline (speedup 1.0000x reference)
#include <cuda_runtime.h>
#include <cstdint>

// Problem constants (fixed by the dataset)
#define NMAX 50000
#define CIN  128
#define C2   256
#define COUT 128
#define KNB  16
#define TILE_R 16

// Scratch: y = BN(relu(f@W1+b1)), z = y@Ws  (51.2 MB each; static device arrays, no allocation)
__device__ float g_y[(size_t)NMAX * C2];
__device__ float g_z[(size_t)NMAX * C2];
__device__ int   g_idx64;   // 1 if neighbor_idx is int64, 0 if int32

// ---------------------------------------------------------------------------
// Detector: neighbor_idx dtype. int64 little-endian -> every odd 32-bit word
// is the (zero) high half. For int32 the odd words are random indices in
// [0, 50000) so the probability all 128 probed words are zero is ~0.
// ---------------------------------------------------------------------------
__global__ void detect_idx_kernel(const unsigned int* __restrict__ p) {
    if (threadIdx.x == 0 && blockIdx.x == 0) {
        int is64 = 1;
        #pragma unroll 1
        for (int t = 1; t < 256; t += 2) {
            if (p[t] != 0u) { is64 = 0; break; }
        }
        g_idx64 = is64;
    }
}

// ---------------------------------------------------------------------------
// Kernel A: per 16-row tile, compute
//   y = (relu(f @ W1 + b1) - mean) * (gamma*rsqrt(var+eps)) + beta
//   z = y @ Ws
// 256 threads; thread owns output channel c, accumulates 16 rows in registers.
// Inner loop: 1 coalesced LDG of the weight + 16 broadcast LDS + 16 FFMA.
// ---------------------------------------------------------------------------
__global__ __launch_bounds__(256) void kernelA(
    const float* __restrict__ f,
    const float* __restrict__ W1,
    const float* __restrict__ b1,
    const float* __restrict__ gamma,
    const float* __restrict__ beta,
    const float* __restrict__ rmean,
    const float* __restrict__ rvar,
    const float* __restrict__ Ws,
    int N)
{
    __shared__ float fs[TILE_R * CIN];   // 8 KB
    __shared__ float ys[TILE_R * C2];    // 16 KB

    const int row0 = blockIdx.x * TILE_R;
    const int c = threadIdx.x;

    // Stage features tile (coalesced)
    for (int t = threadIdx.x; t < TILE_R * CIN; t += 256) {
        int r = t >> 7;          // /128
        int i = t & (CIN - 1);
        int gr = row0 + r;
        fs[t] = (gr < N) ? f[(size_t)gr * CIN + i] : 0.f;
    }
    __syncthreads();

    // GEMM 1: y_tile = f_tile @ W1
    float acc[TILE_R];
    #pragma unroll
    for (int r = 0; r < TILE_R; r++) acc[r] = 0.f;

    #pragma unroll 4
    for (int i = 0; i < CIN; i++) {
        float w = W1[i * C2 + c];
        #pragma unroll
        for (int r = 0; r < TILE_R; r++)
            acc[r] = fmaf(fs[r * CIN + i], w, acc[r]);
    }

    // bias + relu + BN affine; stage y tile and write y to global
    {
        float bb  = b1[c];
        float inv = gamma[c] * rsqrtf(rvar[c] + 1e-5f);
        float mu  = rmean[c];
        float bt  = beta[c];
        #pragma unroll
        for (int r = 0; r < TILE_R; r++) {
            float v = fmaxf(acc[r] + bb, 0.f);
            v = (v - mu) * inv + bt;
            ys[r * C2 + c] = v;
            int gr = row0 + r;
            if (gr < N) g_y[(size_t)gr * C2 + c] = v;
        }
    }
    __syncthreads();

    // GEMM 2: z_tile = y_tile @ Ws
    #pragma unroll
    for (int r = 0; r < TILE_R; r++) acc[r] = 0.f;

    #pragma unroll 4
    for (int i = 0; i < C2; i++) {
        float w = Ws[i * C2 + c];
        #pragma unroll
        for (int r = 0; r < TILE_R; r++)
            acc[r] = fmaf(ys[r * C2 + i], w, acc[r]);
    }

    #pragma unroll
    for (int r = 0; r < TILE_R; r++) {
        int gr = row0 + r;
        if (gr < N) g_z[(size_t)gr * C2 + c] = acc[r];
    }
}

// ---------------------------------------------------------------------------
// Kernel B: one warp per node.
//   logits[k,c] = z[idx[k]][c]  (precomputed!)
//   softmax over k per channel, weighted sum with y rows -> feat (256)
//   out = feat @ Wm + bm
// Lane owns channels {4*lane..4*lane+3} and {128+4*lane..+3} (float4 gathers).
// ---------------------------------------------------------------------------
__global__ __launch_bounds__(256) void kernelB(
    const void* __restrict__ idxp,
    const float* __restrict__ Wm,
    const float* __restrict__ bm,
    float* __restrict__ out,
    int N)
{
    __shared__ float feat[8][C2];   // 8 KB; each warp uses only its own row

    const int wl   = threadIdx.x >> 5;
    const int lane = threadIdx.x & 31;
    const int n    = blockIdx.x * 8 + wl;
    if (n >= N) return;   // whole-warp exit; no block-level sync used below

    const int is64 = g_idx64;

    // Load the 16 neighbor indices (lanes 0..15), broadcast via shfl
    int my = 0;
    if (lane < KNB) {
        if (is64) my = (int)((const long long*)idxp)[(size_t)n * KNB + lane];
        else      my = ((const int*)idxp)[(size_t)n * KNB + lane];
    }
    int nb[KNB];
    #pragma unroll
    for (int k = 0; k < KNB; k++)
        nb[k] = __shfl_sync(0xffffffffu, my, k);

    // Pass 1: per-channel max over the 16 neighbors
    float m[8];
    #pragma unroll
    for (int q = 0; q < 8; q++) m[q] = -1e30f;

    #pragma unroll
    for (int k = 0; k < KNB; k++) {
        const float4* zr = (const float4*)(g_z + (size_t)nb[k] * C2);
        #pragma unroll
        for (int h = 0; h < 2; h++) {
            float4 a = zr[h * 32 + lane];
            const float* ap = (const float*)&a;
            #pragma unroll
            for (int j = 0; j < 4; j++) {
                int q = h * 4 + j;
                m[q] = fmaxf(m[q], ap[j]);
            }
        }
    }

    // Pass 2: exp-sum and weighted accumulation with y (z rows re-read: L1 hits)
    float s[8], fa[8];
    #pragma unroll
    for (int q = 0; q < 8; q++) { s[q] = 0.f; fa[q] = 0.f; }

    #pragma unroll
    for (int k = 0; k < KNB; k++) {
        const float4* zr = (const float4*)(g_z + (size_t)nb[k] * C2);
        const float4* yr = (const float4*)(g_y + (size_t)nb[k] * C2);
        #pragma unroll
        for (int h = 0; h < 2; h++) {
            float4 a  = zr[h * 32 + lane];
            float4 ya = yr[h * 32 + lane];
            const float* ap = (const float*)&a;
            const float* yp = (const float*)&ya;
            #pragma unroll
            for (int j = 0; j < 4; j++) {
                int q = h * 4 + j;
                float e = __expf(ap[j] - m[q]);
                s[q]  += e;
                fa[q] = fmaf(e, yp[j], fa[q]);
            }
        }
    }

    // Normalize and stage feat in shared (channel layout: 4*lane.. and 128+4*lane..)
    {
        float4 r0, r1;
        r0.x = fa[0] / s[0]; r0.y = fa[1] / s[1]; r0.z = fa[2] / s[2]; r0.w = fa[3] / s[3];
        r1.x = fa[4] / s[4]; r1.y = fa[5] / s[5]; r1.z = fa[6] / s[6]; r1.w = fa[7] / s[7];
        ((float4*)feat[wl])[lane]      = r0;
        ((float4*)feat[wl])[32 + lane] = r1;
    }
    __syncwarp();

    // Final matmul: out[n] = feat @ Wm + bm. Lane owns 4 consecutive outputs.
    float4 o = ((const float4*)bm)[lane];
    #pragma unroll 4
    for (int i = 0; i < C2; i++) {
        float fv = feat[wl][i];                                  // broadcast LDS
        float4 w = ((const float4*)(Wm + (size_t)i * COUT))[lane]; // LDG.128, coalesced
        o.x = fmaf(fv, w.x, o.x);
        o.y = fmaf(fv, w.y, o.y);
        o.z = fmaf(fv, w.z, o.z);
        o.w = fmaf(fv, w.w, o.w);
    }
    ((float4*)(out + (size_t)n * COUT))[lane] = o;
}

// ---------------------------------------------------------------------------
// Launch
// Inputs (metadata order): 0 features, 1 neighbor_idx, 2 W1, 3 b1, 4 gamma,
// 5 beta, 6 run_mean, 7 run_var, 8 Ws, 9 Wm, 10 bm. Output: (N,128) float32.
// ---------------------------------------------------------------------------
extern "C" void kernel_launch(void* const* d_in, const int* in_sizes, int n_in,
                              void* d_out, int out_size)
{
    const float* f     = (const float*)d_in[0];
    const void*  idxp  = (const void*) d_in[1];
    const float* W1    = (const float*)d_in[2];
    const float* b1    = (const float*)d_in[3];
    const float* gamma = (const float*)d_in[4];
    const float* beta  = (const float*)d_in[5];
    const float* rmean = (const float*)d_in[6];
    const float* rvar  = (const float*)d_in[7];
    const float* Ws    = (const float*)d_in[8];
    const float* Wm    = (const float*)d_in[9];
    const float* bm    = (const float*)d_in[10];
    float* out = (float*)d_out;

    const int N = in_sizes[0] / CIN;

    detect_idx_kernel<<<1, 32>>>((const unsigned int*)idxp);

    int gridA = (N + TILE_R - 1) / TILE_R;
    kernelA<<<gridA, 256>>>(f, W1, b1, gamma, beta, rmean, rvar, Ws, N);

    int gridB = (N + 7) / 8;
    kernelB<<<gridB, 256>>>(idxp, Wm, bm, out, N);
}

// round 2
// speedup vs baseline: 1.0302x; 1.0302x over previous
#include <cuda_runtime.h>
#include <cstdint>

// Problem constants (fixed by the dataset)
#define NMAX 50000
#define CIN  128
#define C2   256
#define COUT 128
#define KNB  16
#define TILE_R 16

// Scratch (static device arrays; no allocation):
//   g_e = exp(z)        where z = BN(relu(f@W1+b1)) @ Ws
//   g_q = exp(z) * y    elementwise (softmax numerator terms)
__device__ float g_e[(size_t)NMAX * C2];
__device__ float g_q[(size_t)NMAX * C2];
__device__ int   g_idx64;   // 1 if neighbor_idx is int64, 0 if int32

// ---------------------------------------------------------------------------
// Detector: neighbor_idx dtype. int64 little-endian -> every odd 32-bit word
// is the (zero) high half. For int32 the odd words are random indices in
// [0, 50000) so the probability all 128 probed words are zero is ~0.
// ---------------------------------------------------------------------------
__global__ void detect_idx_kernel(const unsigned int* __restrict__ p) {
    if (threadIdx.x == 0 && blockIdx.x == 0) {
        int is64 = 1;
        #pragma unroll 1
        for (int t = 1; t < 256; t += 2) {
            if (p[t] != 0u) { is64 = 0; break; }
        }
        g_idx64 = is64;
    }
}

// ---------------------------------------------------------------------------
// Kernel A: per 16-row tile:
//   y = (relu(f @ W1 + b1) - mean) * (gamma*rsqrt(var+eps)) + beta
//   z = y @ Ws ;  e = exp(z) ; q = e * y   -> global
// 256 threads; thread owns output channel c, accumulates 16 rows in registers.
// Inner loop: 1 coalesced LDG + 16 broadcast LDS + 16 FFMA (FMA-pipe bound).
// ---------------------------------------------------------------------------
__global__ __launch_bounds__(256) void kernelA(
    const float* __restrict__ f,
    const float* __restrict__ W1,
    const float* __restrict__ b1,
    const float* __restrict__ gamma,
    const float* __restrict__ beta,
    const float* __restrict__ rmean,
    const float* __restrict__ rvar,
    const float* __restrict__ Ws,
    int N)
{
    __shared__ float fs[TILE_R * CIN];   // 8 KB
    __shared__ float ys[TILE_R * C2];    // 16 KB

    const int row0 = blockIdx.x * TILE_R;
    const int c = threadIdx.x;

    // Stage features tile (coalesced)
    for (int t = threadIdx.x; t < TILE_R * CIN; t += 256) {
        int r = t >> 7;          // /128
        int i = t & (CIN - 1);
        int gr = row0 + r;
        fs[t] = (gr < N) ? f[(size_t)gr * CIN + i] : 0.f;
    }
    __syncthreads();

    // GEMM 1: y_tile = f_tile @ W1
    float acc[TILE_R];
    #pragma unroll
    for (int r = 0; r < TILE_R; r++) acc[r] = 0.f;

    #pragma unroll 4
    for (int i = 0; i < CIN; i++) {
        float w = W1[i * C2 + c];
        #pragma unroll
        for (int r = 0; r < TILE_R; r++)
            acc[r] = fmaf(fs[r * CIN + i], w, acc[r]);
    }

    // bias + relu + BN affine; stage y tile in shared
    {
        float bb  = b1[c];
        float inv = gamma[c] * rsqrtf(rvar[c] + 1e-5f);
        float mu  = rmean[c];
        float bt  = beta[c];
        #pragma unroll
        for (int r = 0; r < TILE_R; r++) {
            float v = fmaxf(acc[r] + bb, 0.f);
            ys[r * C2 + c] = (v - mu) * inv + bt;
        }
    }
    __syncthreads();

    // GEMM 2: z_tile = y_tile @ Ws ; epilogue e = exp(z), q = e*y
    #pragma unroll
    for (int r = 0; r < TILE_R; r++) acc[r] = 0.f;

    #pragma unroll 4
    for (int i = 0; i < C2; i++) {
        float w = Ws[i * C2 + c];
        #pragma unroll
        for (int r = 0; r < TILE_R; r++)
            acc[r] = fmaf(ys[r * C2 + i], w, acc[r]);
    }

    #pragma unroll
    for (int r = 0; r < TILE_R; r++) {
        int gr = row0 + r;
        if (gr < N) {
            float e = __expf(acc[r]);
            g_e[(size_t)gr * C2 + c] = e;
            g_q[(size_t)gr * C2 + c] = e * ys[r * C2 + c];
        }
    }
}

// ---------------------------------------------------------------------------
// Kernel B: block = 8 nodes, 256 threads.
// Phase 1 (warp per node): gather e and q rows for the 16 neighbors,
//   den[c] = sum_k e[nb_k][c], num[c] = sum_k q[nb_k][c], feat = num/den.
//   (exp precomputed in kernel A; softmax needs no max-shift here.)
// Phase 2 (block-cooperative): out[8][128] = feat[8][256] @ Wm + bm.
//   Thread owns (col c, 4 nodes); Wm loads coalesced 1 wf/warp;
//   feat via broadcast LDS.128. FMA-pipe bound.
// ---------------------------------------------------------------------------
__global__ __launch_bounds__(256) void kernelB(
    const void* __restrict__ idxp,
    const float* __restrict__ Wm,
    const float* __restrict__ bm,
    float* __restrict__ out,
    int N)
{
    __shared__ float feat[8][C2];   // 8 KB

    const int wl   = threadIdx.x >> 5;
    const int lane = threadIdx.x & 31;
    const int n    = blockIdx.x * 8 + wl;
    const int nc   = (n < N) ? n : (N - 1);   // clamp; stores are guarded

    const int is64 = g_idx64;

    // Load the 16 neighbor indices (lanes 0..15), broadcast via shfl
    int my = 0;
    if (lane < KNB) {
        if (is64) my = (int)((const long long*)idxp)[(size_t)nc * KNB + lane];
        else      my = ((const int*)idxp)[(size_t)nc * KNB + lane];
    }
    int nb[KNB];
    #pragma unroll
    for (int k = 0; k < KNB; k++)
        nb[k] = __shfl_sync(0xffffffffu, my, k);

    // Single-pass gather-accumulate (lane owns channels 4*lane.. and 128+4*lane..)
    float den[8], num[8];
    #pragma unroll
    for (int q = 0; q < 8; q++) { den[q] = 0.f; num[q] = 0.f; }

    #pragma unroll 4
    for (int k = 0; k < KNB; k++) {
        const float4* er = (const float4*)(g_e + (size_t)nb[k] * C2);
        const float4* qr = (const float4*)(g_q + (size_t)nb[k] * C2);
        #pragma unroll
        for (int h = 0; h < 2; h++) {
            float4 e4 = er[h * 32 + lane];
            float4 q4 = qr[h * 32 + lane];
            den[h*4+0] += e4.x;  num[h*4+0] += q4.x;
            den[h*4+1] += e4.y;  num[h*4+1] += q4.y;
            den[h*4+2] += e4.z;  num[h*4+2] += q4.z;
            den[h*4+3] += e4.w;  num[h*4+3] += q4.w;
        }
    }

    // feat = num / den -> shared
    {
        float4 r0, r1;
        r0.x = num[0] / den[0]; r0.y = num[1] / den[1];
        r0.z = num[2] / den[2]; r0.w = num[3] / den[3];
        r1.x = num[4] / den[4]; r1.y = num[5] / den[5];
        r1.z = num[6] / den[6]; r1.w = num[7] / den[7];
        ((float4*)feat[wl])[lane]      = r0;
        ((float4*)feat[wl])[32 + lane] = r1;
    }
    __syncthreads();

    // Phase 2: out_tile(8x128) = feat(8x256) @ Wm + bm
    const int c = threadIdx.x & 127;      // output column
    const int h = threadIdx.x >> 7;       // node half: nodes 4h..4h+3
    float a0 = 0.f, a1 = 0.f, a2 = 0.f, a3 = 0.f;

    #pragma unroll 4
    for (int i = 0; i < C2; i += 4) {
        float4 f0 = *(const float4*)&feat[4*h + 0][i];   // broadcast LDS.128
        float4 f1 = *(const float4*)&feat[4*h + 1][i];
        float4 f2 = *(const float4*)&feat[4*h + 2][i];
        float4 f3 = *(const float4*)&feat[4*h + 3][i];
        float w0 = Wm[(size_t)(i + 0) * COUT + c];       // coalesced, 1 wf/warp
        float w1 = Wm[(size_t)(i + 1) * COUT + c];
        float w2 = Wm[(size_t)(i + 2) * COUT + c];
        float w3 = Wm[(size_t)(i + 3) * COUT + c];
        a0 = fmaf(f0.x, w0, a0); a0 = fmaf(f0.y, w1, a0);
        a0 = fmaf(f0.z, w2, a0); a0 = fmaf(f0.w, w3, a0);
        a1 = fmaf(f1.x, w0, a1); a1 = fmaf(f1.y, w1, a1);
        a1 = fmaf(f1.z, w2, a1); a1 = fmaf(f1.w, w3, a1);
        a2 = fmaf(f2.x, w0, a2); a2 = fmaf(f2.y, w1, a2);
        a2 = fmaf(f2.z, w2, a2); a2 = fmaf(f2.w, w3, a2);
        a3 = fmaf(f3.x, w0, a3); a3 = fmaf(f3.y, w1, a3);
        a3 = fmaf(f3.z, w2, a3); a3 = fmaf(f3.w, w3, a3);
    }

    const int nodebase = blockIdx.x * 8 + 4 * h;
    const float bb = bm[c];
    if (nodebase + 0 < N) out[(size_t)(nodebase + 0) * COUT + c] = a0 + bb;
    if (nodebase + 1 < N) out[(size_t)(nodebase + 1) * COUT + c] = a1 + bb;
    if (nodebase + 2 < N) out[(size_t)(nodebase + 2) * COUT + c] = a2 + bb;
    if (nodebase + 3 < N) out[(size_t)(nodebase + 3) * COUT + c] = a3 + bb;
}

// ---------------------------------------------------------------------------
// Launch
// Inputs (metadata order): 0 features, 1 neighbor_idx, 2 W1, 3 b1, 4 gamma,
// 5 beta, 6 run_mean, 7 run_var, 8 Ws, 9 Wm, 10 bm. Output: (N,128) float32.
// ---------------------------------------------------------------------------
extern "C" void kernel_launch(void* const* d_in, const int* in_sizes, int n_in,
                              void* d_out, int out_size)
{
    const float* f     = (const float*)d_in[0];
    const void*  idxp  = (const void*) d_in[1];
    const float* W1    = (const float*)d_in[2];
    const float* b1    = (const float*)d_in[3];
    const float* gamma = (const float*)d_in[4];
    const float* beta  = (const float*)d_in[5];
    const float* rmean = (const float*)d_in[6];
    const float* rvar  = (const float*)d_in[7];
    const float* Ws    = (const float*)d_in[8];
    const float* Wm    = (const float*)d_in[9];
    const float* bm    = (const float*)d_in[10];
    float* out = (float*)d_out;

    const int N = in_sizes[0] / CIN;

    detect_idx_kernel<<<1, 32>>>((const unsigned int*)idxp);

    int gridA = (N + TILE_R - 1) / TILE_R;
    kernelA<<<gridA, 256>>>(f, W1, b1, gamma, beta, rmean, rvar, Ws, N);

    int gridB = (N + 7) / 8;
    kernelB<<<gridB, 256>>>(idxp, Wm, bm, out, N);
}

// round 3
// speedup vs baseline: 1.6697x; 1.6208x over previous
#include <cuda_runtime.h>
#include <cstdint>

// Problem constants (fixed by the dataset)
#define NMAX 50000
#define CIN  128
#define C2   256
#define COUT 128
#define KNB  16
#define ROWS_A 32
#define KCHUNK 16

// Scratch (static device arrays; no allocation):
//   g_e = exp(z)        where z = BN(relu(f@W1+b1)) @ Ws
//   g_q = exp(z) * y    elementwise (softmax numerator terms)
__device__ float g_e[(size_t)NMAX * C2];
__device__ float g_q[(size_t)NMAX * C2];
__device__ int   g_idx64;   // 1 if neighbor_idx is int64, 0 if int32

// ---------------------------------------------------------------------------
// Kernel A: per 32-row tile (256 threads, thread owns 4 rows x 8 cols):
//   y = BN(relu(f @ W1 + b1)) ; z = y @ Ws ; e = exp(z) ; q = e*y -> global
// Register-blocked GEMM: per k-step 4 broadcast LDS + 2 LDS.128 + 32 FFMA
// (FFMA-pipe bound, 75% smem crossbar). Weights staged in 16-k chunks.
// Thread cols: {4tc..4tc+3} and {128+4tc..131+4tc} so b-frag LDS.128 and all
// stores are lane-contiguous (4 wavefronts each).
// ---------------------------------------------------------------------------
__global__ __launch_bounds__(256) void kernelA(
    const float* __restrict__ f,
    const float* __restrict__ W1,
    const float* __restrict__ b1,
    const float* __restrict__ gamma,
    const float* __restrict__ beta,
    const float* __restrict__ rmean,
    const float* __restrict__ rvar,
    const float* __restrict__ Ws,
    const unsigned int* __restrict__ idx_raw,
    int N)
{
    __shared__ float U[ROWS_A * C2];     // 32KB: phase1 = fs[32][128], then ys[32][256]
    __shared__ float Wt[KCHUNK][C2];     // 16KB weight chunk

    // Fold idx-dtype detection into kernel A (saves a launch; B reads g_idx64)
    if (blockIdx.x == 0 && threadIdx.x == 0) {
        int is64 = 1;
        #pragma unroll 1
        for (int t = 1; t < 256; t += 2)
            if (idx_raw[t] != 0u) { is64 = 0; break; }
        g_idx64 = is64;
    }

    const int row0 = blockIdx.x * ROWS_A;
    const int tr = threadIdx.x >> 5;     // 0..7  -> rows 4tr..4tr+3
    const int tc = threadIdx.x & 31;     // cols 4tc..+3 and 128+4tc..+3

    // Stage features row-major (coalesced)
    for (int t = threadIdx.x; t < ROWS_A * CIN; t += 256) {
        int r = t >> 7, i = t & 127;
        int gr = row0 + r;
        U[r * CIN + i] = (gr < N) ? f[(size_t)gr * CIN + i] : 0.f;
    }

    float acc[4][8];
    #pragma unroll
    for (int rr = 0; rr < 4; rr++)
        #pragma unroll
        for (int j = 0; j < 8; j++) acc[rr][j] = 0.f;

    // ---- GEMM 1: pre = fs @ W1 ----
    for (int k0 = 0; k0 < CIN; k0 += KCHUNK) {
        __syncthreads();   // also covers initial fs staging at k0==0
        #pragma unroll
        for (int s = 0; s < (KCHUNK * C2 / 4) / 256; s++) {   // 4 float4 per thread
            int t = threadIdx.x + s * 256;
            int kk = t >> 6, cc = t & 63;
            ((float4*)&Wt[kk][0])[cc] =
                ((const float4*)(W1 + (size_t)(k0 + kk) * C2))[cc];
        }
        __syncthreads();
        #pragma unroll 4
        for (int kk = 0; kk < KCHUNK; kk++) {
            int k = k0 + kk;
            float a0 = U[(4*tr + 0) * CIN + k];
            float a1 = U[(4*tr + 1) * CIN + k];
            float a2 = U[(4*tr + 2) * CIN + k];
            float a3 = U[(4*tr + 3) * CIN + k];
            float4 bl = *(const float4*)&Wt[kk][4*tc];
            float4 bh = *(const float4*)&Wt[kk][128 + 4*tc];
            acc[0][0]=fmaf(a0,bl.x,acc[0][0]); acc[0][1]=fmaf(a0,bl.y,acc[0][1]);
            acc[0][2]=fmaf(a0,bl.z,acc[0][2]); acc[0][3]=fmaf(a0,bl.w,acc[0][3]);
            acc[0][4]=fmaf(a0,bh.x,acc[0][4]); acc[0][5]=fmaf(a0,bh.y,acc[0][5]);
            acc[0][6]=fmaf(a0,bh.z,acc[0][6]); acc[0][7]=fmaf(a0,bh.w,acc[0][7]);
            acc[1][0]=fmaf(a1,bl.x,acc[1][0]); acc[1][1]=fmaf(a1,bl.y,acc[1][1]);
            acc[1][2]=fmaf(a1,bl.z,acc[1][2]); acc[1][3]=fmaf(a1,bl.w,acc[1][3]);
            acc[1][4]=fmaf(a1,bh.x,acc[1][4]); acc[1][5]=fmaf(a1,bh.y,acc[1][5]);
            acc[1][6]=fmaf(a1,bh.z,acc[1][6]); acc[1][7]=fmaf(a1,bh.w,acc[1][7]);
            acc[2][0]=fmaf(a2,bl.x,acc[2][0]); acc[2][1]=fmaf(a2,bl.y,acc[2][1]);
            acc[2][2]=fmaf(a2,bl.z,acc[2][2]); acc[2][3]=fmaf(a2,bl.w,acc[2][3]);
            acc[2][4]=fmaf(a2,bh.x,acc[2][4]); acc[2][5]=fmaf(a2,bh.y,acc[2][5]);
            acc[2][6]=fmaf(a2,bh.z,acc[2][6]); acc[2][7]=fmaf(a2,bh.w,acc[2][7]);
            acc[3][0]=fmaf(a3,bl.x,acc[3][0]); acc[3][1]=fmaf(a3,bl.y,acc[3][1]);
            acc[3][2]=fmaf(a3,bl.z,acc[3][2]); acc[3][3]=fmaf(a3,bl.w,acc[3][3]);
            acc[3][4]=fmaf(a3,bh.x,acc[3][4]); acc[3][5]=fmaf(a3,bh.y,acc[3][5]);
            acc[3][6]=fmaf(a3,bh.z,acc[3][6]); acc[3][7]=fmaf(a3,bh.w,acc[3][7]);
        }
    }

    // ---- Epilogue 1: bias + relu + BN -> y (in acc), stage ys into U ----
    {
        float4 pb_l  = *(const float4*)(b1    + 4*tc);
        float4 pb_h  = *(const float4*)(b1    + 128 + 4*tc);
        float4 pg_l  = *(const float4*)(gamma + 4*tc);
        float4 pg_h  = *(const float4*)(gamma + 128 + 4*tc);
        float4 pbt_l = *(const float4*)(beta  + 4*tc);
        float4 pbt_h = *(const float4*)(beta  + 128 + 4*tc);
        float4 pm_l  = *(const float4*)(rmean + 4*tc);
        float4 pm_h  = *(const float4*)(rmean + 128 + 4*tc);
        float4 pv_l  = *(const float4*)(rvar  + 4*tc);
        float4 pv_h  = *(const float4*)(rvar  + 128 + 4*tc);
        float vb[8]  = {pb_l.x,pb_l.y,pb_l.z,pb_l.w,pb_h.x,pb_h.y,pb_h.z,pb_h.w};
        float vg[8]  = {pg_l.x,pg_l.y,pg_l.z,pg_l.w,pg_h.x,pg_h.y,pg_h.z,pg_h.w};
        float vbt[8] = {pbt_l.x,pbt_l.y,pbt_l.z,pbt_l.w,pbt_h.x,pbt_h.y,pbt_h.z,pbt_h.w};
        float vm[8]  = {pm_l.x,pm_l.y,pm_l.z,pm_l.w,pm_h.x,pm_h.y,pm_h.z,pm_h.w};
        float vv[8]  = {pv_l.x,pv_l.y,pv_l.z,pv_l.w,pv_h.x,pv_h.y,pv_h.z,pv_h.w};
        #pragma unroll
        for (int j = 0; j < 8; j++) {
            float inv = vg[j] * rsqrtf(vv[j] + 1e-5f);
            #pragma unroll
            for (int rr = 0; rr < 4; rr++) {
                float v = fmaxf(acc[rr][j] + vb[j], 0.f);
                acc[rr][j] = (v - vm[j]) * inv + vbt[j];
            }
        }
    }
    __syncthreads();   // all fs reads done before overwriting U with ys
    #pragma unroll
    for (int rr = 0; rr < 4; rr++) {
        *(float4*)&U[(4*tr + rr) * C2 + 4*tc] =
            make_float4(acc[rr][0], acc[rr][1], acc[rr][2], acc[rr][3]);
        *(float4*)&U[(4*tr + rr) * C2 + 128 + 4*tc] =
            make_float4(acc[rr][4], acc[rr][5], acc[rr][6], acc[rr][7]);
    }

    // ---- GEMM 2: z = ys @ Ws ----
    #pragma unroll
    for (int rr = 0; rr < 4; rr++)
        #pragma unroll
        for (int j = 0; j < 8; j++) acc[rr][j] = 0.f;

    for (int k0 = 0; k0 < C2; k0 += KCHUNK) {
        __syncthreads();
        #pragma unroll
        for (int s = 0; s < (KCHUNK * C2 / 4) / 256; s++) {
            int t = threadIdx.x + s * 256;
            int kk = t >> 6, cc = t & 63;
            ((float4*)&Wt[kk][0])[cc] =
                ((const float4*)(Ws + (size_t)(k0 + kk) * C2))[cc];
        }
        __syncthreads();
        #pragma unroll 4
        for (int kk = 0; kk < KCHUNK; kk++) {
            int k = k0 + kk;
            float a0 = U[(4*tr + 0) * C2 + k];
            float a1 = U[(4*tr + 1) * C2 + k];
            float a2 = U[(4*tr + 2) * C2 + k];
            float a3 = U[(4*tr + 3) * C2 + k];
            float4 bl = *(const float4*)&Wt[kk][4*tc];
            float4 bh = *(const float4*)&Wt[kk][128 + 4*tc];
            acc[0][0]=fmaf(a0,bl.x,acc[0][0]); acc[0][1]=fmaf(a0,bl.y,acc[0][1]);
            acc[0][2]=fmaf(a0,bl.z,acc[0][2]); acc[0][3]=fmaf(a0,bl.w,acc[0][3]);
            acc[0][4]=fmaf(a0,bh.x,acc[0][4]); acc[0][5]=fmaf(a0,bh.y,acc[0][5]);
            acc[0][6]=fmaf(a0,bh.z,acc[0][6]); acc[0][7]=fmaf(a0,bh.w,acc[0][7]);
            acc[1][0]=fmaf(a1,bl.x,acc[1][0]); acc[1][1]=fmaf(a1,bl.y,acc[1][1]);
            acc[1][2]=fmaf(a1,bl.z,acc[1][2]); acc[1][3]=fmaf(a1,bl.w,acc[1][3]);
            acc[1][4]=fmaf(a1,bh.x,acc[1][4]); acc[1][5]=fmaf(a1,bh.y,acc[1][5]);
            acc[1][6]=fmaf(a1,bh.z,acc[1][6]); acc[1][7]=fmaf(a1,bh.w,acc[1][7]);
            acc[2][0]=fmaf(a2,bl.x,acc[2][0]); acc[2][1]=fmaf(a2,bl.y,acc[2][1]);
            acc[2][2]=fmaf(a2,bl.z,acc[2][2]); acc[2][3]=fmaf(a2,bl.w,acc[2][3]);
            acc[2][4]=fmaf(a2,bh.x,acc[2][4]); acc[2][5]=fmaf(a2,bh.y,acc[2][5]);
            acc[2][6]=fmaf(a2,bh.z,acc[2][6]); acc[2][7]=fmaf(a2,bh.w,acc[2][7]);
            acc[3][0]=fmaf(a3,bl.x,acc[3][0]); acc[3][1]=fmaf(a3,bl.y,acc[3][1]);
            acc[3][2]=fmaf(a3,bl.z,acc[3][2]); acc[3][3]=fmaf(a3,bl.w,acc[3][3]);
            acc[3][4]=fmaf(a3,bh.x,acc[3][4]); acc[3][5]=fmaf(a3,bh.y,acc[3][5]);
            acc[3][6]=fmaf(a3,bh.z,acc[3][6]); acc[3][7]=fmaf(a3,bh.w,acc[3][7]);
        }
    }

    // ---- Epilogue 2: e = exp(z), q = e*y (y re-read from U), store ----
    #pragma unroll
    for (int rr = 0; rr < 4; rr++) {
        int gr = row0 + 4*tr + rr;
        if (gr < N) {
            float4 yl = *(const float4*)&U[(4*tr + rr) * C2 + 4*tc];
            float4 yh = *(const float4*)&U[(4*tr + rr) * C2 + 128 + 4*tc];
            float4 el, eh, ql, qh;
            el.x = __expf(acc[rr][0]); el.y = __expf(acc[rr][1]);
            el.z = __expf(acc[rr][2]); el.w = __expf(acc[rr][3]);
            eh.x = __expf(acc[rr][4]); eh.y = __expf(acc[rr][5]);
            eh.z = __expf(acc[rr][6]); eh.w = __expf(acc[rr][7]);
            ql.x = el.x * yl.x; ql.y = el.y * yl.y; ql.z = el.z * yl.z; ql.w = el.w * yl.w;
            qh.x = eh.x * yh.x; qh.y = eh.y * yh.y; qh.z = eh.z * yh.z; qh.w = eh.w * yh.w;
            *(float4*)(g_e + (size_t)gr * C2 + 4*tc)       = el;
            *(float4*)(g_e + (size_t)gr * C2 + 128 + 4*tc) = eh;
            *(float4*)(g_q + (size_t)gr * C2 + 4*tc)       = ql;
            *(float4*)(g_q + (size_t)gr * C2 + 128 + 4*tc) = qh;
        }
    }
}

// ---------------------------------------------------------------------------
// Kernel B: block = 8 nodes, 256 threads.
// Phase 1 (warp per node): single-pass gather of e,q rows -> feat = num/den.
// Phase 2 (block-cooperative): out[8][128] = feat[8][256] @ Wm + bm.
// ---------------------------------------------------------------------------
__global__ __launch_bounds__(256) void kernelB(
    const void* __restrict__ idxp,
    const float* __restrict__ Wm,
    const float* __restrict__ bm,
    float* __restrict__ out,
    int N)
{
    __shared__ float feat[8][C2];   // 8 KB

    const int wl   = threadIdx.x >> 5;
    const int lane = threadIdx.x & 31;
    const int n    = blockIdx.x * 8 + wl;
    const int nc   = (n < N) ? n : (N - 1);   // clamp; stores are guarded

    const int is64 = g_idx64;

    int my = 0;
    if (lane < KNB) {
        if (is64) my = (int)((const long long*)idxp)[(size_t)nc * KNB + lane];
        else      my = ((const int*)idxp)[(size_t)nc * KNB + lane];
    }
    int nb[KNB];
    #pragma unroll
    for (int k = 0; k < KNB; k++)
        nb[k] = __shfl_sync(0xffffffffu, my, k);

    float den[8], num[8];
    #pragma unroll
    for (int q = 0; q < 8; q++) { den[q] = 0.f; num[q] = 0.f; }

    #pragma unroll 4
    for (int k = 0; k < KNB; k++) {
        const float4* er = (const float4*)(g_e + (size_t)nb[k] * C2);
        const float4* qr = (const float4*)(g_q + (size_t)nb[k] * C2);
        #pragma unroll
        for (int h = 0; h < 2; h++) {
            float4 e4 = er[h * 32 + lane];
            float4 q4 = qr[h * 32 + lane];
            den[h*4+0] += e4.x;  num[h*4+0] += q4.x;
            den[h*4+1] += e4.y;  num[h*4+1] += q4.y;
            den[h*4+2] += e4.z;  num[h*4+2] += q4.z;
            den[h*4+3] += e4.w;  num[h*4+3] += q4.w;
        }
    }

    {
        float4 r0, r1;
        r0.x = num[0] / den[0]; r0.y = num[1] / den[1];
        r0.z = num[2] / den[2]; r0.w = num[3] / den[3];
        r1.x = num[4] / den[4]; r1.y = num[5] / den[5];
        r1.z = num[6] / den[6]; r1.w = num[7] / den[7];
        ((float4*)feat[wl])[lane]      = r0;
        ((float4*)feat[wl])[32 + lane] = r1;
    }
    __syncthreads();

    // Phase 2: out_tile(8x128) = feat(8x256) @ Wm + bm
    const int c = threadIdx.x & 127;      // output column
    const int h = threadIdx.x >> 7;       // node half: nodes 4h..4h+3
    float a0 = 0.f, a1 = 0.f, a2 = 0.f, a3 = 0.f;

    #pragma unroll 4
    for (int i = 0; i < C2; i += 4) {
        float4 f0 = *(const float4*)&feat[4*h + 0][i];   // broadcast LDS.128
        float4 f1 = *(const float4*)&feat[4*h + 1][i];
        float4 f2 = *(const float4*)&feat[4*h + 2][i];
        float4 f3 = *(const float4*)&feat[4*h + 3][i];
        float w0 = Wm[(size_t)(i + 0) * COUT + c];       // coalesced
        float w1 = Wm[(size_t)(i + 1) * COUT + c];
        float w2 = Wm[(size_t)(i + 2) * COUT + c];
        float w3 = Wm[(size_t)(i + 3) * COUT + c];
        a0 = fmaf(f0.x, w0, a0); a0 = fmaf(f0.y, w1, a0);
        a0 = fmaf(f0.z, w2, a0); a0 = fmaf(f0.w, w3, a0);
        a1 = fmaf(f1.x, w0, a1); a1 = fmaf(f1.y, w1, a1);
        a1 = fmaf(f1.z, w2, a1); a1 = fmaf(f1.w, w3, a1);
        a2 = fmaf(f2.x, w0, a2); a2 = fmaf(f2.y, w1, a2);
        a2 = fmaf(f2.z, w2, a2); a2 = fmaf(f2.w, w3, a2);
        a3 = fmaf(f3.x, w0, a3); a3 = fmaf(f3.y, w1, a3);
        a3 = fmaf(f3.z, w2, a3); a3 = fmaf(f3.w, w3, a3);
    }

    const int nodebase = blockIdx.x * 8 + 4 * h;
    const float bb = bm[c];
    if (nodebase + 0 < N) out[(size_t)(nodebase + 0) * COUT + c] = a0 + bb;
    if (nodebase + 1 < N) out[(size_t)(nodebase + 1) * COUT + c] = a1 + bb;
    if (nodebase + 2 < N) out[(size_t)(nodebase + 2) * COUT + c] = a2 + bb;
    if (nodebase + 3 < N) out[(size_t)(nodebase + 3) * COUT + c] = a3 + bb;
}

// ---------------------------------------------------------------------------
// Launch
// ---------------------------------------------------------------------------
extern "C" void kernel_launch(void* const* d_in, const int* in_sizes, int n_in,
                              void* d_out, int out_size)
{
    const float* f     = (const float*)d_in[0];
    const void*  idxp  = (const void*) d_in[1];
    const float* W1    = (const float*)d_in[2];
    const float* b1    = (const float*)d_in[3];
    const float* gamma = (const float*)d_in[4];
    const float* beta  = (const float*)d_in[5];
    const float* rmean = (const float*)d_in[6];
    const float* rvar  = (const float*)d_in[7];
    const float* Ws    = (const float*)d_in[8];
    const float* Wm    = (const float*)d_in[9];
    const float* bm    = (const float*)d_in[10];
    float* out = (float*)d_out;

    const int N = in_sizes[0] / CIN;

    int gridA = (N + ROWS_A - 1) / ROWS_A;
    kernelA<<<gridA, 256>>>(f, W1, b1, gamma, beta, rmean, rvar, Ws,
                            (const unsigned int*)idxp, N);

    int gridB = (N + 7) / 8;
    kernelB<<<gridB, 256>>>(idxp, Wm, bm, out, N);
}

// round 5
// speedup vs baseline: 2.0799x; 1.2456x over previous
#include <cuda_runtime.h>
#include <cuda_bf16.h>
#include <cstdint>

// Problem constants (fixed by the dataset)
#define NMAX 50000
#define CIN  128
#define C2   256
#define COUT 128
#define KNB  16

// Scratch (static device arrays; no allocation):
__device__ float g_e[(size_t)NMAX * C2];          // exp(z)
__device__ float g_q[(size_t)NMAX * C2];          // exp(z)*y
__device__ __nv_bfloat16 g_W1h[256 * 128];        // W1^T hi  [n][k]
__device__ __nv_bfloat16 g_W1l[256 * 128];        // W1^T lo
__device__ __nv_bfloat16 g_Wsh[256 * 256];        // Ws^T hi  [n][k]
__device__ __nv_bfloat16 g_Wsl[256 * 256];        // Ws^T lo
__device__ int g_idx64;

// ---------------------------------------------------------------------------
// mma.sync m16n8k16 bf16 (sm_80 baseline PTX; valid on compute_103)
// Fragment layout (canonical): g = lane>>2, kt = lane&3
//   A: a0={A[g][2kt],A[g][2kt+1]} a1={A[g+8][..]} a2={A[g][2kt+8,+9]} a3={A[g+8][2kt+8,+9]}
//   B: b0={B[2kt][n],B[2kt+1][n]} b1={B[2kt+8][n],B[2kt+9][n]}, n=g  (col-major = [n][k] storage)
//   D: d0=D[g][2kt] d1=D[g][2kt+1] d2=D[g+8][2kt] d3=D[g+8][2kt+1]
// ---------------------------------------------------------------------------
__device__ __forceinline__ void mma16816(float* d,
    uint32_t a0, uint32_t a1, uint32_t a2, uint32_t a3,
    uint32_t b0, uint32_t b1)
{
    asm volatile(
        "mma.sync.aligned.m16n8k16.row.col.f32.bf16.bf16.f32 "
        "{%0,%1,%2,%3}, {%4,%5,%6,%7}, {%8,%9}, {%0,%1,%2,%3};"
        : "+f"(d[0]), "+f"(d[1]), "+f"(d[2]), "+f"(d[3])
        : "r"(a0), "r"(a1), "r"(a2), "r"(a3), "r"(b0), "r"(b1));
}

// SMEM layout (bytes). Strides 272/528 are ≡4 mod 32 in words => conflict-free
// fragment LDS ((4g+kt)%32 all-distinct).
#define XS   272      // X row stride (128 bf16 + pad)
#define XH_OFF 0
#define XL_OFF 17408              // 64*272
#define YS   528      // ys row stride (256 bf16 + pad)
#define YSH_OFF 0
#define YSL_OFF 33792             // 64*528
#define WS   272      // weight tile row stride (128 bf16 + pad)
#define W_OFF 69632
#define WHL  69632                // 256*272 (hi block size; lo follows)
#define PAR_OFF 208896
#define SMEM_TOTAL 212992

// ---------------------------------------------------------------------------
// Prep: pack W1^T, Ws^T as bf16 hi/lo, [n][k] k-contiguous; idx dtype detect.
// ---------------------------------------------------------------------------
__global__ __launch_bounds__(256) void prep_kernel(
    const float* __restrict__ W1,
    const float* __restrict__ Ws,
    const unsigned int* __restrict__ idxraw)
{
    const int b = blockIdx.x, tid = threadIdx.x;
    if (b == 0 && tid == 0) {   // int64 -> every odd 32-bit word zero
        int is64 = 1;
        #pragma unroll 1
        for (int t = 1; t < 256; t += 2)
            if (idxraw[t] != 0u) { is64 = 0; break; }
        g_idx64 = is64;
    }
    if (b < 2) {                 // W1: 32768 elems, 16384 per block
        #pragma unroll 4
        for (int i = 0; i < 64; i++) {
            int idx = b * 16384 + tid + i * 256;
            int k = idx >> 8, n = idx & 255;
            float v = W1[(size_t)k * 256 + n];          // coalesced over n
            __nv_bfloat16 hi = __float2bfloat16(v);
            g_W1h[n * 128 + k] = hi;
            g_W1l[n * 128 + k] = __float2bfloat16(v - __bfloat162float(hi));
        }
    } else {                     // Ws: 65536 elems, blocks 2..5
        #pragma unroll 4
        for (int i = 0; i < 64; i++) {
            int idx = (b - 2) * 16384 + tid + i * 256;
            int k = idx >> 8, n = idx & 255;
            float v = Ws[(size_t)k * 256 + n];
            __nv_bfloat16 hi = __float2bfloat16(v);
            g_Wsh[n * 256 + k] = hi;
            g_Wsl[n * 256 + k] = __float2bfloat16(v - __bfloat162float(hi));
        }
    }
}

// ---------------------------------------------------------------------------
// kernelA_mma: block = 64 rows x 256 cols, 8 warps (4 M-strips x 2 N-halves).
//   GEMM1: pre = X @ W1 (bf16 hi/lo 3-MMA split, fp32 accum)
//   BN epilogue in-reg -> ys bf16 hi/lo to smem
//   GEMM2: z = ys @ Ws (2 staged K-chunks)
//   epilogue: e = exp(z), q = e*y -> STG.64 frag-direct
// ---------------------------------------------------------------------------
__global__ __launch_bounds__(256, 1) void kernelA_mma(
    const float* __restrict__ f,
    const float* __restrict__ b1, const float* __restrict__ gamma,
    const float* __restrict__ beta, const float* __restrict__ rmean,
    const float* __restrict__ rvar, int N)
{
    extern __shared__ unsigned char smem[];
    const int tid = threadIdx.x, wid = tid >> 5, lane = tid & 31;
    const int ms = wid & 3, nh = wid >> 2;
    const int g = lane >> 2, kt = lane & 3;
    const int row0 = blockIdx.x * 64;

    float* Pb  = (float*)(smem + PAR_OFF);
    float* Pinv = Pb + 256; float* Pmu = Pinv + 256; float* Pbt = Pmu + 256;
    {
        int c = tid;
        Pb[c]   = b1[c];
        Pinv[c] = gamma[c] * rsqrtf(rvar[c] + 1e-5f);
        Pmu[c]  = rmean[c];
        Pbt[c]  = beta[c];
    }

    // ---- Stage X (64x128 f32 -> bf16 hi/lo, strided rows) ----
    #pragma unroll
    for (int i = 0; i < 8; i++) {
        int fi = tid + i * 256;            // 2048 float4 total
        int r = fi >> 5, c4 = fi & 31;
        float4 v = make_float4(0.f, 0.f, 0.f, 0.f);
        if (row0 + r < N) v = ((const float4*)(f + (size_t)(row0 + r) * CIN))[c4];
        __nv_bfloat162 h0 = __floats2bfloat162_rn(v.x, v.y);
        __nv_bfloat162 h1 = __floats2bfloat162_rn(v.z, v.w);
        __nv_bfloat162 l0 = __floats2bfloat162_rn(v.x - __bfloat162float(h0.x),
                                                  v.y - __bfloat162float(h0.y));
        __nv_bfloat162 l1 = __floats2bfloat162_rn(v.z - __bfloat162float(h1.x),
                                                  v.w - __bfloat162float(h1.y));
        uint2 hu, lu;
        hu.x = *(uint32_t*)&h0; hu.y = *(uint32_t*)&h1;
        lu.x = *(uint32_t*)&l0; lu.y = *(uint32_t*)&l1;
        *(uint2*)(smem + XH_OFF + r * XS + c4 * 8) = hu;
        *(uint2*)(smem + XL_OFF + r * XS + c4 * 8) = lu;
    }
    // ---- Stage W1 (hi+lo: 2 x 256 rows x 16 uint4) ----
    #pragma unroll
    for (int i = 0; i < 32; i++) {
        int u = tid + i * 256;             // 8192 uint4
        int half = u >> 12, r = (u >> 4) & 255, c = u & 15;
        const uint4* src = (const uint4*)(half ? (const void*)g_W1l : (const void*)g_W1h);
        *(uint4*)(smem + W_OFF + half * WHL + r * WS + c * 16) = src[r * 16 + c];
    }
    __syncthreads();

    float acc[16][4];
    #pragma unroll
    for (int t = 0; t < 16; t++)
        #pragma unroll
        for (int j = 0; j < 4; j++) acc[t][j] = 0.f;

    // ---- GEMM 1: K = 128 ----
    {
        const unsigned char* Ah = smem + XH_OFF + (16 * ms + g) * XS + kt * 4;
        const unsigned char* Al = smem + XL_OFF + (16 * ms + g) * XS + kt * 4;
        const unsigned char* Bb = smem + W_OFF + (nh * 128 + g) * WS + kt * 4;
        #pragma unroll 1
        for (int ks = 0; ks < 8; ks++) {
            const int kb = ks * 32;        // 16 k = 32 bytes
            uint32_t ah0 = *(const uint32_t*)(Ah + kb);
            uint32_t ah1 = *(const uint32_t*)(Ah + kb + 8 * XS);
            uint32_t ah2 = *(const uint32_t*)(Ah + kb + 16);
            uint32_t ah3 = *(const uint32_t*)(Ah + kb + 8 * XS + 16);
            uint32_t al0 = *(const uint32_t*)(Al + kb);
            uint32_t al1 = *(const uint32_t*)(Al + kb + 8 * XS);
            uint32_t al2 = *(const uint32_t*)(Al + kb + 16);
            uint32_t al3 = *(const uint32_t*)(Al + kb + 8 * XS + 16);
            #pragma unroll
            for (int t = 0; t < 16; t++) {
                const unsigned char* Bp = Bb + t * 8 * WS + kb;
                uint32_t bh0 = *(const uint32_t*)(Bp);
                uint32_t bh1 = *(const uint32_t*)(Bp + 16);
                uint32_t bl0 = *(const uint32_t*)(Bp + WHL);
                uint32_t bl1 = *(const uint32_t*)(Bp + WHL + 16);
                mma16816(acc[t], ah0, ah1, ah2, ah3, bh0, bh1);
                mma16816(acc[t], ah0, ah1, ah2, ah3, bl0, bl1);
                mma16816(acc[t], al0, al1, al2, al3, bh0, bh1);
            }
        }
    }
    __syncthreads();   // all GEMM1 reads done before overwriting X area with ys

    // ---- BN epilogue -> ys hi/lo (smem) ----
    #pragma unroll
    for (int t = 0; t < 16; t++) {
        const int nc0 = nh * 128 + t * 8 + 2 * kt;
        float2 pb  = *(const float2*)&Pb[nc0];
        float2 pin = *(const float2*)&Pinv[nc0];
        float2 pmu = *(const float2*)&Pmu[nc0];
        float2 pbt = *(const float2*)&Pbt[nc0];
        float y00 = (fmaxf(acc[t][0] + pb.x, 0.f) - pmu.x) * pin.x + pbt.x;
        float y01 = (fmaxf(acc[t][1] + pb.y, 0.f) - pmu.y) * pin.y + pbt.y;
        float y10 = (fmaxf(acc[t][2] + pb.x, 0.f) - pmu.x) * pin.x + pbt.x;
        float y11 = (fmaxf(acc[t][3] + pb.y, 0.f) - pmu.y) * pin.y + pbt.y;
        __nv_bfloat162 h0 = __floats2bfloat162_rn(y00, y01);
        __nv_bfloat162 h1 = __floats2bfloat162_rn(y10, y11);
        __nv_bfloat162 l0 = __floats2bfloat162_rn(y00 - __bfloat162float(h0.x),
                                                  y01 - __bfloat162float(h0.y));
        __nv_bfloat162 l1 = __floats2bfloat162_rn(y10 - __bfloat162float(h1.x),
                                                  y11 - __bfloat162float(h1.y));
        const int r0 = 16 * ms + g;
        *(uint32_t*)(smem + YSH_OFF + r0 * YS + nc0 * 2)       = *(uint32_t*)&h0;
        *(uint32_t*)(smem + YSH_OFF + (r0 + 8) * YS + nc0 * 2) = *(uint32_t*)&h1;
        *(uint32_t*)(smem + YSL_OFF + r0 * YS + nc0 * 2)       = *(uint32_t*)&l0;
        *(uint32_t*)(smem + YSL_OFF + (r0 + 8) * YS + nc0 * 2) = *(uint32_t*)&l1;
    }

    // ---- GEMM 2: K = 256 in 2 staged chunks ----
    #pragma unroll
    for (int t = 0; t < 16; t++)
        #pragma unroll
        for (int j = 0; j < 4; j++) acc[t][j] = 0.f;

    #pragma unroll 1
    for (int chunk = 0; chunk < 2; chunk++) {
        __syncthreads();   // previous W reads (and ys STS at chunk 0) complete
        #pragma unroll
        for (int i = 0; i < 32; i++) {
            int u = tid + i * 256;
            int half = u >> 12, r = (u >> 4) & 255, c = u & 15;
            const unsigned char* src =
                (const unsigned char*)(half ? (const void*)g_Wsl : (const void*)g_Wsh)
                + (size_t)r * 512 + chunk * 256 + c * 16;
            *(uint4*)(smem + W_OFF + half * WHL + r * WS + c * 16) = *(const uint4*)src;
        }
        __syncthreads();

        const unsigned char* Ah = smem + YSH_OFF + (16 * ms + g) * YS + chunk * 256 + kt * 4;
        const unsigned char* Al = smem + YSL_OFF + (16 * ms + g) * YS + chunk * 256 + kt * 4;
        const unsigned char* Bb = smem + W_OFF + (nh * 128 + g) * WS + kt * 4;
        #pragma unroll 1
        for (int ks = 0; ks < 8; ks++) {
            const int kb = ks * 32;
            uint32_t ah0 = *(const uint32_t*)(Ah + kb);
            uint32_t ah1 = *(const uint32_t*)(Ah + kb + 8 * YS);
            uint32_t ah2 = *(const uint32_t*)(Ah + kb + 16);
            uint32_t ah3 = *(const uint32_t*)(Ah + kb + 8 * YS + 16);
            uint32_t al0 = *(const uint32_t*)(Al + kb);
            uint32_t al1 = *(const uint32_t*)(Al + kb + 8 * YS);
            uint32_t al2 = *(const uint32_t*)(Al + kb + 16);
            uint32_t al3 = *(const uint32_t*)(Al + kb + 8 * YS + 16);
            #pragma unroll
            for (int t = 0; t < 16; t++) {
                const unsigned char* Bp = Bb + t * 8 * WS + kb;
                uint32_t bh0 = *(const uint32_t*)(Bp);
                uint32_t bh1 = *(const uint32_t*)(Bp + 16);
                uint32_t bl0 = *(const uint32_t*)(Bp + WHL);
                uint32_t bl1 = *(const uint32_t*)(Bp + WHL + 16);
                mma16816(acc[t], ah0, ah1, ah2, ah3, bh0, bh1);
                mma16816(acc[t], ah0, ah1, ah2, ah3, bl0, bl1);
                mma16816(acc[t], al0, al1, al2, al3, bh0, bh1);
            }
        }
    }

    // ---- Final epilogue: e = exp(z), q = e*y; frag-direct STG.64 ----
    #pragma unroll
    for (int t = 0; t < 16; t++) {
        const int nc0 = nh * 128 + t * 8 + 2 * kt;
        const int r0 = 16 * ms + g;
        uint32_t yh0 = *(const uint32_t*)(smem + YSH_OFF + r0 * YS + nc0 * 2);
        uint32_t yl0 = *(const uint32_t*)(smem + YSL_OFF + r0 * YS + nc0 * 2);
        uint32_t yh1 = *(const uint32_t*)(smem + YSH_OFF + (r0 + 8) * YS + nc0 * 2);
        uint32_t yl1 = *(const uint32_t*)(smem + YSL_OFF + (r0 + 8) * YS + nc0 * 2);
        __nv_bfloat162 h0 = *(__nv_bfloat162*)&yh0, l0 = *(__nv_bfloat162*)&yl0;
        __nv_bfloat162 h1 = *(__nv_bfloat162*)&yh1, l1 = *(__nv_bfloat162*)&yl1;
        float y00 = __bfloat162float(h0.x) + __bfloat162float(l0.x);
        float y01 = __bfloat162float(h0.y) + __bfloat162float(l0.y);
        float y10 = __bfloat162float(h1.x) + __bfloat162float(l1.x);
        float y11 = __bfloat162float(h1.y) + __bfloat162float(l1.y);
        float e00 = __expf(acc[t][0]), e01 = __expf(acc[t][1]);
        float e10 = __expf(acc[t][2]), e11 = __expf(acc[t][3]);
        int gr0 = row0 + r0, gr1 = gr0 + 8;
        if (gr0 < N) {
            *(float2*)(g_e + (size_t)gr0 * C2 + nc0) = make_float2(e00, e01);
            *(float2*)(g_q + (size_t)gr0 * C2 + nc0) = make_float2(e00 * y00, e01 * y01);
        }
        if (gr1 < N) {
            *(float2*)(g_e + (size_t)gr1 * C2 + nc0) = make_float2(e10, e11);
            *(float2*)(g_q + (size_t)gr1 * C2 + nc0) = make_float2(e10 * y10, e11 * y11);
        }
    }
}

// ---------------------------------------------------------------------------
// Kernel B (unchanged from R3): warp-per-node gather of e,q; block GEMM @ Wm.
// ---------------------------------------------------------------------------
__global__ __launch_bounds__(256) void kernelB(
    const void* __restrict__ idxp,
    const float* __restrict__ Wm,
    const float* __restrict__ bm,
    float* __restrict__ out,
    int N)
{
    __shared__ float feat[8][C2];

    const int wl   = threadIdx.x >> 5;
    const int lane = threadIdx.x & 31;
    const int n    = blockIdx.x * 8 + wl;
    const int ncl  = (n < N) ? n : (N - 1);

    const int is64 = g_idx64;

    int my = 0;
    if (lane < KNB) {
        if (is64) my = (int)((const long long*)idxp)[(size_t)ncl * KNB + lane];
        else      my = ((const int*)idxp)[(size_t)ncl * KNB + lane];
    }
    int nb[KNB];
    #pragma unroll
    for (int k = 0; k < KNB; k++)
        nb[k] = __shfl_sync(0xffffffffu, my, k);

    float den[8], num[8];
    #pragma unroll
    for (int q = 0; q < 8; q++) { den[q] = 0.f; num[q] = 0.f; }

    #pragma unroll 4
    for (int k = 0; k < KNB; k++) {
        const float4* er = (const float4*)(g_e + (size_t)nb[k] * C2);
        const float4* qr = (const float4*)(g_q + (size_t)nb[k] * C2);
        #pragma unroll
        for (int h = 0; h < 2; h++) {
            float4 e4 = er[h * 32 + lane];
            float4 q4 = qr[h * 32 + lane];
            den[h*4+0] += e4.x;  num[h*4+0] += q4.x;
            den[h*4+1] += e4.y;  num[h*4+1] += q4.y;
            den[h*4+2] += e4.z;  num[h*4+2] += q4.z;
            den[h*4+3] += e4.w;  num[h*4+3] += q4.w;
        }
    }

    {
        float4 r0, r1;
        r0.x = num[0] / den[0]; r0.y = num[1] / den[1];
        r0.z = num[2] / den[2]; r0.w = num[3] / den[3];
        r1.x = num[4] / den[4]; r1.y = num[5] / den[5];
        r1.z = num[6] / den[6]; r1.w = num[7] / den[7];
        ((float4*)feat[wl])[lane]      = r0;
        ((float4*)feat[wl])[32 + lane] = r1;
    }
    __syncthreads();

    const int c = threadIdx.x & 127;
    const int h = threadIdx.x >> 7;
    float a0 = 0.f, a1 = 0.f, a2 = 0.f, a3 = 0.f;

    #pragma unroll 4
    for (int i = 0; i < C2; i += 4) {
        float4 f0 = *(const float4*)&feat[4*h + 0][i];
        float4 f1 = *(const float4*)&feat[4*h + 1][i];
        float4 f2 = *(const float4*)&feat[4*h + 2][i];
        float4 f3 = *(const float4*)&feat[4*h + 3][i];
        float w0 = Wm[(size_t)(i + 0) * COUT + c];
        float w1 = Wm[(size_t)(i + 1) * COUT + c];
        float w2 = Wm[(size_t)(i + 2) * COUT + c];
        float w3 = Wm[(size_t)(i + 3) * COUT + c];
        a0 = fmaf(f0.x, w0, a0); a0 = fmaf(f0.y, w1, a0);
        a0 = fmaf(f0.z, w2, a0); a0 = fmaf(f0.w, w3, a0);
        a1 = fmaf(f1.x, w0, a1); a1 = fmaf(f1.y, w1, a1);
        a1 = fmaf(f1.z, w2, a1); a1 = fmaf(f1.w, w3, a1);
        a2 = fmaf(f2.x, w0, a2); a2 = fmaf(f2.y, w1, a2);
        a2 = fmaf(f2.z, w2, a2); a2 = fmaf(f2.w, w3, a2);
        a3 = fmaf(f3.x, w0, a3); a3 = fmaf(f3.y, w1, a3);
        a3 = fmaf(f3.z, w2, a3); a3 = fmaf(f3.w, w3, a3);
    }

    const int nodebase = blockIdx.x * 8 + 4 * h;
    const float bb = bm[c];
    if (nodebase + 0 < N) out[(size_t)(nodebase + 0) * COUT + c] = a0 + bb;
    if (nodebase + 1 < N) out[(size_t)(nodebase + 1) * COUT + c] = a1 + bb;
    if (nodebase + 2 < N) out[(size_t)(nodebase + 2) * COUT + c] = a2 + bb;
    if (nodebase + 3 < N) out[(size_t)(nodebase + 3) * COUT + c] = a3 + bb;
}

// ---------------------------------------------------------------------------
// Launch
// ---------------------------------------------------------------------------
extern "C" void kernel_launch(void* const* d_in, const int* in_sizes, int n_in,
                              void* d_out, int out_size)
{
    const float* f     = (const float*)d_in[0];
    const void*  idxp  = (const void*) d_in[1];
    const float* W1    = (const float*)d_in[2];
    const float* b1    = (const float*)d_in[3];
    const float* gamma = (const float*)d_in[4];
    const float* beta  = (const float*)d_in[5];
    const float* rmean = (const float*)d_in[6];
    const float* rvar  = (const float*)d_in[7];
    const float* Ws    = (const float*)d_in[8];
    const float* Wm    = (const float*)d_in[9];
    const float* bm    = (const float*)d_in[10];
    float* out = (float*)d_out;

    const int N = in_sizes[0] / CIN;

    static int attr_set = 0;
    if (!attr_set) {
        cudaFuncSetAttribute(kernelA_mma,
                             cudaFuncAttributeMaxDynamicSharedMemorySize, SMEM_TOTAL);
        attr_set = 1;
    }

    prep_kernel<<<6, 256>>>(W1, Ws, (const unsigned int*)idxp);
    kernelA_mma<<<(N + 63) / 64, 256, SMEM_TOTAL>>>(f, b1, gamma, beta, rmean, rvar, N);
    kernelB<<<(N + 7) / 8, 256>>>(idxp, Wm, bm, out, N);
}

// round 6
// speedup vs baseline: 2.8935x; 1.3912x over previous
#include <cuda_runtime.h>
#include <cuda_bf16.h>
#include <cuda_fp16.h>
#include <cstdint>

// Problem constants (fixed by the dataset)
#define NMAX 50000
#define CIN  128
#define C2   256
#define COUT 128
#define KNB  16

// Scratch (static device arrays; no allocation):
// g_eq[node]: 256 half = e = exp(z), then 256 half = q = e*y  (1KB per node)
__device__ __half g_eq[(size_t)NMAX * 512];
__device__ __nv_bfloat16 g_W1h[256 * 128];        // W1^T hi  [n][k]
__device__ __nv_bfloat16 g_W1l[256 * 128];        // W1^T lo
__device__ __nv_bfloat16 g_Wsh[256 * 256];        // Ws^T hi  [n][k]
__device__ __nv_bfloat16 g_Wsl[256 * 256];        // Ws^T lo
__device__ int g_idx64;

// ---------------------------------------------------------------------------
// mma.sync m16n8k16 bf16 (baseline PTX, valid on compute_103 virtual arch)
// ---------------------------------------------------------------------------
__device__ __forceinline__ void mma16816(float* d,
    uint32_t a0, uint32_t a1, uint32_t a2, uint32_t a3,
    uint32_t b0, uint32_t b1)
{
    asm volatile(
        "mma.sync.aligned.m16n8k16.row.col.f32.bf16.bf16.f32 "
        "{%0,%1,%2,%3}, {%4,%5,%6,%7}, {%8,%9}, {%0,%1,%2,%3};"
        : "+f"(d[0]), "+f"(d[1]), "+f"(d[2]), "+f"(d[3])
        : "r"(a0), "r"(a1), "r"(a2), "r"(a3), "r"(b0), "r"(b1));
}

// SMEM layout (bytes). Strides 272/528 ≡ 4 mod 32 words => conflict-free frags.
#define XS   272
#define XH_OFF 0
#define XL_OFF 17408              // 64*272
#define YS   528
#define YSH_OFF 0
#define YSL_OFF 33792             // 64*528
#define WS   272
#define W_OFF 69632
#define WHL  69632                // 256*272
#define PAR_OFF 208896
#define SMEM_TOTAL 212992

// ---------------------------------------------------------------------------
// Prep: pack W1^T, Ws^T bf16 hi/lo, [n][k]; idx dtype detect. 24 blocks.
// ---------------------------------------------------------------------------
__global__ __launch_bounds__(256) void prep_kernel(
    const float* __restrict__ W1,
    const float* __restrict__ Ws,
    const unsigned int* __restrict__ idxraw)
{
    const int b = blockIdx.x, tid = threadIdx.x;
    if (b == 0 && tid == 0) {   // int64 -> every odd 32-bit word zero
        int is64 = 1;
        #pragma unroll 1
        for (int t = 1; t < 256; t += 2)
            if (idxraw[t] != 0u) { is64 = 0; break; }
        g_idx64 = is64;
    }
    if (b < 8) {                 // W1: 32768 elems, 4096 per block
        #pragma unroll
        for (int i = 0; i < 16; i++) {
            int idx = b * 4096 + tid + i * 256;
            int k = idx >> 8, n = idx & 255;
            float v = W1[(size_t)k * 256 + n];
            __nv_bfloat16 hi = __float2bfloat16(v);
            g_W1h[n * 128 + k] = hi;
            g_W1l[n * 128 + k] = __float2bfloat16(v - __bfloat162float(hi));
        }
    } else {                     // Ws: 65536 elems, blocks 8..23
        #pragma unroll
        for (int i = 0; i < 16; i++) {
            int idx = (b - 8) * 4096 + tid + i * 256;
            int k = idx >> 8, n = idx & 255;
            float v = Ws[(size_t)k * 256 + n];
            __nv_bfloat16 hi = __float2bfloat16(v);
            g_Wsh[n * 256 + k] = hi;
            g_Wsl[n * 256 + k] = __float2bfloat16(v - __bfloat162float(hi));
        }
    }
}

// ---------------------------------------------------------------------------
// kernelA_mma: block = 64 rows x 256 cols, 8 warps (4 M x 2 N).
// GEMM1 (X@W1, bf16 hi/lo 3-MMA) -> BN -> ys (smem) -> GEMM2 (ys@Ws)
// -> epilogue e=exp(z), q=e*y stored fp16 interleaved.
// ---------------------------------------------------------------------------
__global__ __launch_bounds__(256, 1) void kernelA_mma(
    const float* __restrict__ f,
    const float* __restrict__ b1, const float* __restrict__ gamma,
    const float* __restrict__ beta, const float* __restrict__ rmean,
    const float* __restrict__ rvar, int N)
{
    extern __shared__ unsigned char smem[];
    const int tid = threadIdx.x, wid = tid >> 5, lane = tid & 31;
    const int ms = wid & 3, nh = wid >> 2;
    const int g = lane >> 2, kt = lane & 3;
    const int row0 = blockIdx.x * 64;

    float* Pb  = (float*)(smem + PAR_OFF);
    float* Pinv = Pb + 256; float* Pmu = Pinv + 256; float* Pbt = Pmu + 256;
    {
        int c = tid;
        Pb[c]   = b1[c];
        Pinv[c] = gamma[c] * rsqrtf(rvar[c] + 1e-5f);
        Pmu[c]  = rmean[c];
        Pbt[c]  = beta[c];
    }

    // Stage X (64x128 f32 -> bf16 hi/lo)
    #pragma unroll
    for (int i = 0; i < 8; i++) {
        int fi = tid + i * 256;
        int r = fi >> 5, c4 = fi & 31;
        float4 v = make_float4(0.f, 0.f, 0.f, 0.f);
        if (row0 + r < N) v = ((const float4*)(f + (size_t)(row0 + r) * CIN))[c4];
        __nv_bfloat162 h0 = __floats2bfloat162_rn(v.x, v.y);
        __nv_bfloat162 h1 = __floats2bfloat162_rn(v.z, v.w);
        __nv_bfloat162 l0 = __floats2bfloat162_rn(v.x - __bfloat162float(h0.x),
                                                  v.y - __bfloat162float(h0.y));
        __nv_bfloat162 l1 = __floats2bfloat162_rn(v.z - __bfloat162float(h1.x),
                                                  v.w - __bfloat162float(h1.y));
        uint2 hu, lu;
        hu.x = *(uint32_t*)&h0; hu.y = *(uint32_t*)&h1;
        lu.x = *(uint32_t*)&l0; lu.y = *(uint32_t*)&l1;
        *(uint2*)(smem + XH_OFF + r * XS + c4 * 8) = hu;
        *(uint2*)(smem + XL_OFF + r * XS + c4 * 8) = lu;
    }
    // Stage W1
    #pragma unroll
    for (int i = 0; i < 32; i++) {
        int u = tid + i * 256;
        int half_ = u >> 12, r = (u >> 4) & 255, c = u & 15;
        const uint4* src = (const uint4*)(half_ ? (const void*)g_W1l : (const void*)g_W1h);
        *(uint4*)(smem + W_OFF + half_ * WHL + r * WS + c * 16) = src[r * 16 + c];
    }
    __syncthreads();

    float acc[16][4];
    #pragma unroll
    for (int t = 0; t < 16; t++)
        #pragma unroll
        for (int j = 0; j < 4; j++) acc[t][j] = 0.f;

    // GEMM 1: K = 128
    {
        const unsigned char* Ah = smem + XH_OFF + (16 * ms + g) * XS + kt * 4;
        const unsigned char* Al = smem + XL_OFF + (16 * ms + g) * XS + kt * 4;
        const unsigned char* Bb = smem + W_OFF + (nh * 128 + g) * WS + kt * 4;
        #pragma unroll 1
        for (int ks = 0; ks < 8; ks++) {
            const int kb = ks * 32;
            uint32_t ah0 = *(const uint32_t*)(Ah + kb);
            uint32_t ah1 = *(const uint32_t*)(Ah + kb + 8 * XS);
            uint32_t ah2 = *(const uint32_t*)(Ah + kb + 16);
            uint32_t ah3 = *(const uint32_t*)(Ah + kb + 8 * XS + 16);
            uint32_t al0 = *(const uint32_t*)(Al + kb);
            uint32_t al1 = *(const uint32_t*)(Al + kb + 8 * XS);
            uint32_t al2 = *(const uint32_t*)(Al + kb + 16);
            uint32_t al3 = *(const uint32_t*)(Al + kb + 8 * XS + 16);
            #pragma unroll
            for (int t = 0; t < 16; t++) {
                const unsigned char* Bp = Bb + t * 8 * WS + kb;
                uint32_t bh0 = *(const uint32_t*)(Bp);
                uint32_t bh1 = *(const uint32_t*)(Bp + 16);
                uint32_t bl0 = *(const uint32_t*)(Bp + WHL);
                uint32_t bl1 = *(const uint32_t*)(Bp + WHL + 16);
                mma16816(acc[t], ah0, ah1, ah2, ah3, bh0, bh1);
                mma16816(acc[t], ah0, ah1, ah2, ah3, bl0, bl1);
                mma16816(acc[t], al0, al1, al2, al3, bh0, bh1);
            }
        }
    }
    __syncthreads();

    // BN epilogue -> ys hi/lo (smem)
    #pragma unroll
    for (int t = 0; t < 16; t++) {
        const int nc0 = nh * 128 + t * 8 + 2 * kt;
        float2 pb  = *(const float2*)&Pb[nc0];
        float2 pin = *(const float2*)&Pinv[nc0];
        float2 pmu = *(const float2*)&Pmu[nc0];
        float2 pbt = *(const float2*)&Pbt[nc0];
        float y00 = (fmaxf(acc[t][0] + pb.x, 0.f) - pmu.x) * pin.x + pbt.x;
        float y01 = (fmaxf(acc[t][1] + pb.y, 0.f) - pmu.y) * pin.y + pbt.y;
        float y10 = (fmaxf(acc[t][2] + pb.x, 0.f) - pmu.x) * pin.x + pbt.x;
        float y11 = (fmaxf(acc[t][3] + pb.y, 0.f) - pmu.y) * pin.y + pbt.y;
        __nv_bfloat162 h0 = __floats2bfloat162_rn(y00, y01);
        __nv_bfloat162 h1 = __floats2bfloat162_rn(y10, y11);
        __nv_bfloat162 l0 = __floats2bfloat162_rn(y00 - __bfloat162float(h0.x),
                                                  y01 - __bfloat162float(h0.y));
        __nv_bfloat162 l1 = __floats2bfloat162_rn(y10 - __bfloat162float(h1.x),
                                                  y11 - __bfloat162float(h1.y));
        const int r0 = 16 * ms + g;
        *(uint32_t*)(smem + YSH_OFF + r0 * YS + nc0 * 2)       = *(uint32_t*)&h0;
        *(uint32_t*)(smem + YSH_OFF + (r0 + 8) * YS + nc0 * 2) = *(uint32_t*)&h1;
        *(uint32_t*)(smem + YSL_OFF + r0 * YS + nc0 * 2)       = *(uint32_t*)&l0;
        *(uint32_t*)(smem + YSL_OFF + (r0 + 8) * YS + nc0 * 2) = *(uint32_t*)&l1;
    }

    // GEMM 2: K = 256 in 2 staged chunks
    #pragma unroll
    for (int t = 0; t < 16; t++)
        #pragma unroll
        for (int j = 0; j < 4; j++) acc[t][j] = 0.f;

    #pragma unroll 1
    for (int chunk = 0; chunk < 2; chunk++) {
        __syncthreads();
        #pragma unroll
        for (int i = 0; i < 32; i++) {
            int u = tid + i * 256;
            int half_ = u >> 12, r = (u >> 4) & 255, c = u & 15;
            const unsigned char* src =
                (const unsigned char*)(half_ ? (const void*)g_Wsl : (const void*)g_Wsh)
                + (size_t)r * 512 + chunk * 256 + c * 16;
            *(uint4*)(smem + W_OFF + half_ * WHL + r * WS + c * 16) = *(const uint4*)src;
        }
        __syncthreads();

        const unsigned char* Ah = smem + YSH_OFF + (16 * ms + g) * YS + chunk * 256 + kt * 4;
        const unsigned char* Al = smem + YSL_OFF + (16 * ms + g) * YS + chunk * 256 + kt * 4;
        const unsigned char* Bb = smem + W_OFF + (nh * 128 + g) * WS + kt * 4;
        #pragma unroll 1
        for (int ks = 0; ks < 8; ks++) {
            const int kb = ks * 32;
            uint32_t ah0 = *(const uint32_t*)(Ah + kb);
            uint32_t ah1 = *(const uint32_t*)(Ah + kb + 8 * YS);
            uint32_t ah2 = *(const uint32_t*)(Ah + kb + 16);
            uint32_t ah3 = *(const uint32_t*)(Ah + kb + 8 * YS + 16);
            uint32_t al0 = *(const uint32_t*)(Al + kb);
            uint32_t al1 = *(const uint32_t*)(Al + kb + 8 * YS);
            uint32_t al2 = *(const uint32_t*)(Al + kb + 16);
            uint32_t al3 = *(const uint32_t*)(Al + kb + 8 * YS + 16);
            #pragma unroll
            for (int t = 0; t < 16; t++) {
                const unsigned char* Bp = Bb + t * 8 * WS + kb;
                uint32_t bh0 = *(const uint32_t*)(Bp);
                uint32_t bh1 = *(const uint32_t*)(Bp + 16);
                uint32_t bl0 = *(const uint32_t*)(Bp + WHL);
                uint32_t bl1 = *(const uint32_t*)(Bp + WHL + 16);
                mma16816(acc[t], ah0, ah1, ah2, ah3, bh0, bh1);
                mma16816(acc[t], ah0, ah1, ah2, ah3, bl0, bl1);
                mma16816(acc[t], al0, al1, al2, al3, bh0, bh1);
            }
        }
    }

    // Final epilogue: e = exp(z), q = e*y; fp16 interleaved stores
    #pragma unroll
    for (int t = 0; t < 16; t++) {
        const int nc0 = nh * 128 + t * 8 + 2 * kt;
        const int r0 = 16 * ms + g;
        uint32_t yh0 = *(const uint32_t*)(smem + YSH_OFF + r0 * YS + nc0 * 2);
        uint32_t yl0 = *(const uint32_t*)(smem + YSL_OFF + r0 * YS + nc0 * 2);
        uint32_t yh1 = *(const uint32_t*)(smem + YSH_OFF + (r0 + 8) * YS + nc0 * 2);
        uint32_t yl1 = *(const uint32_t*)(smem + YSL_OFF + (r0 + 8) * YS + nc0 * 2);
        __nv_bfloat162 h0 = *(__nv_bfloat162*)&yh0, l0 = *(__nv_bfloat162*)&yl0;
        __nv_bfloat162 h1 = *(__nv_bfloat162*)&yh1, l1 = *(__nv_bfloat162*)&yl1;
        float y00 = __bfloat162float(h0.x) + __bfloat162float(l0.x);
        float y01 = __bfloat162float(h0.y) + __bfloat162float(l0.y);
        float y10 = __bfloat162float(h1.x) + __bfloat162float(l1.x);
        float y11 = __bfloat162float(h1.y) + __bfloat162float(l1.y);
        float e00 = __expf(acc[t][0]), e01 = __expf(acc[t][1]);
        float e10 = __expf(acc[t][2]), e11 = __expf(acc[t][3]);
        int gr0 = row0 + r0, gr1 = gr0 + 8;
        if (gr0 < N) {
            *(__half2*)(g_eq + (size_t)gr0 * 512 + nc0)       = __floats2half2_rn(e00, e01);
            *(__half2*)(g_eq + (size_t)gr0 * 512 + 256 + nc0) = __floats2half2_rn(e00 * y00, e01 * y01);
        }
        if (gr1 < N) {
            *(__half2*)(g_eq + (size_t)gr1 * 512 + nc0)       = __floats2half2_rn(e10, e11);
            *(__half2*)(g_eq + (size_t)gr1 * 512 + 256 + nc0) = __floats2half2_rn(e10 * y10, e11 * y11);
        }
    }
}

// ---------------------------------------------------------------------------
// Kernel B: block = 8 nodes. Phase 1: warp-per-node fp16 gather (2 LDG.128
// per neighbor: 1KB contiguous row), fp32 accumulate, feat = num/den.
// Phase 2: block-cooperative out = feat @ Wm + bm.
// ---------------------------------------------------------------------------
__global__ __launch_bounds__(256) void kernelB(
    const void* __restrict__ idxp,
    const float* __restrict__ Wm,
    const float* __restrict__ bm,
    float* __restrict__ out,
    int N)
{
    __shared__ float feat[8][C2];

    const int wl   = threadIdx.x >> 5;
    const int lane = threadIdx.x & 31;
    const int n    = blockIdx.x * 8 + wl;
    const int ncl  = (n < N) ? n : (N - 1);

    const int is64 = g_idx64;

    int my = 0;
    if (lane < KNB) {
        if (is64) my = (int)((const long long*)idxp)[(size_t)ncl * KNB + lane];
        else      my = ((const int*)idxp)[(size_t)ncl * KNB + lane];
    }
    int nb[KNB];
    #pragma unroll
    for (int k = 0; k < KNB; k++)
        nb[k] = __shfl_sync(0xffffffffu, my, k);

    // Lane owns channels 8*lane .. 8*lane+7
    float den[8], num[8];
    #pragma unroll
    for (int q = 0; q < 8; q++) { den[q] = 0.f; num[q] = 0.f; }

    #pragma unroll 4
    for (int k = 0; k < KNB; k++) {
        const uint4* row = (const uint4*)(g_eq + (size_t)nb[k] * 512);
        uint4 ev = row[lane];        // e halves 8l..8l+7
        uint4 qv = row[32 + lane];   // q halves
        const __half2* eh = (const __half2*)&ev;
        const __half2* qh = (const __half2*)&qv;
        #pragma unroll
        for (int j = 0; j < 4; j++) {
            float2 fe = __half22float2(eh[j]);
            float2 fq = __half22float2(qh[j]);
            den[2*j]   += fe.x;  den[2*j+1] += fe.y;
            num[2*j]   += fq.x;  num[2*j+1] += fq.y;
        }
    }

    {
        float4 r0, r1;
        r0.x = num[0] / den[0]; r0.y = num[1] / den[1];
        r0.z = num[2] / den[2]; r0.w = num[3] / den[3];
        r1.x = num[4] / den[4]; r1.y = num[5] / den[5];
        r1.z = num[6] / den[6]; r1.w = num[7] / den[7];
        ((float4*)feat[wl])[2 * lane]     = r0;
        ((float4*)feat[wl])[2 * lane + 1] = r1;
    }
    __syncthreads();

    const int c = threadIdx.x & 127;
    const int h = threadIdx.x >> 7;
    float a0 = 0.f, a1 = 0.f, a2 = 0.f, a3 = 0.f;

    #pragma unroll 4
    for (int i = 0; i < C2; i += 4) {
        float4 f0 = *(const float4*)&feat[4*h + 0][i];
        float4 f1 = *(const float4*)&feat[4*h + 1][i];
        float4 f2 = *(const float4*)&feat[4*h + 2][i];
        float4 f3 = *(const float4*)&feat[4*h + 3][i];
        float w0 = Wm[(size_t)(i + 0) * COUT + c];
        float w1 = Wm[(size_t)(i + 1) * COUT + c];
        float w2 = Wm[(size_t)(i + 2) * COUT + c];
        float w3 = Wm[(size_t)(i + 3) * COUT + c];
        a0 = fmaf(f0.x, w0, a0); a0 = fmaf(f0.y, w1, a0);
        a0 = fmaf(f0.z, w2, a0); a0 = fmaf(f0.w, w3, a0);
        a1 = fmaf(f1.x, w0, a1); a1 = fmaf(f1.y, w1, a1);
        a1 = fmaf(f1.z, w2, a1); a1 = fmaf(f1.w, w3, a1);
        a2 = fmaf(f2.x, w0, a2); a2 = fmaf(f2.y, w1, a2);
        a2 = fmaf(f2.z, w2, a2); a2 = fmaf(f2.w, w3, a2);
        a3 = fmaf(f3.x, w0, a3); a3 = fmaf(f3.y, w1, a3);
        a3 = fmaf(f3.z, w2, a3); a3 = fmaf(f3.w, w3, a3);
    }

    const int nodebase = blockIdx.x * 8 + 4 * h;
    const float bb = bm[c];
    if (nodebase + 0 < N) out[(size_t)(nodebase + 0) * COUT + c] = a0 + bb;
    if (nodebase + 1 < N) out[(size_t)(nodebase + 1) * COUT + c] = a1 + bb;
    if (nodebase + 2 < N) out[(size_t)(nodebase + 2) * COUT + c] = a2 + bb;
    if (nodebase + 3 < N) out[(size_t)(nodebase + 3) * COUT + c] = a3 + bb;
}

// ---------------------------------------------------------------------------
// Launch
// ---------------------------------------------------------------------------
extern "C" void kernel_launch(void* const* d_in, const int* in_sizes, int n_in,
                              void* d_out, int out_size)
{
    const float* f     = (const float*)d_in[0];
    const void*  idxp  = (const void*) d_in[1];
    const float* W1    = (const float*)d_in[2];
    const float* b1    = (const float*)d_in[3];
    const float* gamma = (const float*)d_in[4];
    const float* beta  = (const float*)d_in[5];
    const float* rmean = (const float*)d_in[6];
    const float* rvar  = (const float*)d_in[7];
    const float* Ws    = (const float*)d_in[8];
    const float* Wm    = (const float*)d_in[9];
    const float* bm    = (const float*)d_in[10];
    float* out = (float*)d_out;

    const int N = in_sizes[0] / CIN;

    static int attr_set = 0;
    if (!attr_set) {
        cudaFuncSetAttribute(kernelA_mma,
                             cudaFuncAttributeMaxDynamicSharedMemorySize, SMEM_TOTAL);
        attr_set = 1;
    }

    prep_kernel<<<24, 256>>>(W1, Ws, (const unsigned int*)idxp);
    kernelA_mma<<<(N + 63) / 64, 256, SMEM_TOTAL>>>(f, b1, gamma, beta, rmean, rvar, N);
    kernelB<<<(N + 7) / 8, 256>>>(idxp, Wm, bm, out, N);
}